// round 1
// baseline (speedup 1.0000x reference)
#include <cuda_runtime.h>
#include <cstdint>

#define B_  4
#define S_  1024
#define D_  1024
#define H_  16
#define HD_ 64
#define M_  (B_*S_)          // 4096 rows for the dense GEMMs

// ---------------- scratch (static __device__, no allocation) ----------------
__device__ float g_q[(size_t)B_*H_*S_*HD_];     // [B,H,S,HD]
__device__ float g_k[(size_t)B_*H_*S_*HD_];
__device__ float g_v[(size_t)B_*H_*S_*HD_];
__device__ float g_ctx[(size_t)M_*D_];          // merged heads [B,S,D]
__device__ float g_attn_fb[(size_t)B_*H_*S_*S_]; // fallback if attn not in d_out

// ============================================================================
// Dense GEMM: Y = X @ W^T + bias.  X [M,K] row-major, W [N,K] row-major.
// 64x64 tile, kTile=16, 256 threads, 4x4 micro-tile.
// MODE 0: write head-split layout [B,H,S,HD]; MODE 1: plain [M,N].
// ============================================================================
template<int MODE>
__global__ void __launch_bounds__(256) proj_kernel(
    const float* __restrict__ X, const float* __restrict__ W,
    const float* __restrict__ bias, float* __restrict__ Y)
{
    const int K = D_;
    __shared__ float As[16][64];   // [k][m]
    __shared__ float Bs[16][64];   // [k][n]
    int tid = threadIdx.x;
    int tx = tid & 15, ty = tid >> 4;
    int bm = blockIdx.x * 64, bn = blockIdx.y * 64;
    int lr = tid >> 2;             // 0..63
    int lc = (tid & 3) * 4;        // 0,4,8,12

    float acc[4][4] = {};
    for (int k0 = 0; k0 < K; k0 += 16) {
        float4 av = *(const float4*)&X[(size_t)(bm + lr) * K + k0 + lc];
        float4 bv = *(const float4*)&W[(size_t)(bn + lr) * K + k0 + lc];
        As[lc+0][lr] = av.x; As[lc+1][lr] = av.y; As[lc+2][lr] = av.z; As[lc+3][lr] = av.w;
        Bs[lc+0][lr] = bv.x; Bs[lc+1][lr] = bv.y; Bs[lc+2][lr] = bv.z; Bs[lc+3][lr] = bv.w;
        __syncthreads();
        #pragma unroll
        for (int kk = 0; kk < 16; kk++) {
            float4 a = *(const float4*)&As[kk][ty*4];
            float4 b = *(const float4*)&Bs[kk][tx*4];
            acc[0][0] += a.x*b.x; acc[0][1] += a.x*b.y; acc[0][2] += a.x*b.z; acc[0][3] += a.x*b.w;
            acc[1][0] += a.y*b.x; acc[1][1] += a.y*b.y; acc[1][2] += a.y*b.z; acc[1][3] += a.y*b.w;
            acc[2][0] += a.z*b.x; acc[2][1] += a.z*b.y; acc[2][2] += a.z*b.z; acc[2][3] += a.z*b.w;
            acc[3][0] += a.w*b.x; acc[3][1] += a.w*b.y; acc[3][2] += a.w*b.z; acc[3][3] += a.w*b.w;
        }
        __syncthreads();
    }
    int nb = bn + tx*4;
    float4 bias4 = *(const float4*)&bias[nb];
    #pragma unroll
    for (int i = 0; i < 4; i++) {
        int m = bm + ty*4 + i;
        float4 o;
        o.x = acc[i][0] + bias4.x; o.y = acc[i][1] + bias4.y;
        o.z = acc[i][2] + bias4.z; o.w = acc[i][3] + bias4.w;
        if (MODE == 0) {
            int b = m >> 10, s = m & 1023;      // S_=1024
            int h = nb >> 6, d = nb & 63;       // HD_=64 (4-aligned, no boundary cross)
            *(float4*)&Y[((((size_t)b*H_ + h)*S_) + s)*HD_ + d] = o;
        } else {
            *(float4*)&Y[(size_t)m*D_ + nb] = o;
        }
    }
}

// ============================================================================
// Scores: per (b,h): S[q,k] = (Q[q,:]·K[k,:]) * 0.125, masked -> attn buffer.
// Full HD=64 in smem.  64x64 output tile per block.
// ============================================================================
__global__ void __launch_bounds__(256) scores_kernel(
    const float* __restrict__ q, const float* __restrict__ k,
    const int* __restrict__ mask, float* __restrict__ attn)
{
    int bh = blockIdx.z;
    int b  = bh / H_;
    const float* Q = q + (size_t)bh * S_ * HD_;
    const float* Kp = k + (size_t)bh * S_ * HD_;
    int bq = blockIdx.x * 64, bk = blockIdx.y * 64;

    __shared__ float Qs[64][64];   // [d][q]
    __shared__ float Ks[64][64];   // [d][k]
    int tid = threadIdx.x;
    int tx = tid & 15, ty = tid >> 4;
    int lr = tid >> 2;

    #pragma unroll
    for (int it = 0; it < 4; it++) {
        int c = (tid & 3) * 4 + it * 16;
        float4 qv = *(const float4*)&Q[(size_t)(bq + lr) * HD_ + c];
        float4 kv = *(const float4*)&Kp[(size_t)(bk + lr) * HD_ + c];
        Qs[c+0][lr] = qv.x; Qs[c+1][lr] = qv.y; Qs[c+2][lr] = qv.z; Qs[c+3][lr] = qv.w;
        Ks[c+0][lr] = kv.x; Ks[c+1][lr] = kv.y; Ks[c+2][lr] = kv.z; Ks[c+3][lr] = kv.w;
    }
    __syncthreads();

    float acc[4][4] = {};
    #pragma unroll
    for (int kk = 0; kk < 64; kk++) {
        float4 a = *(const float4*)&Qs[kk][ty*4];
        float4 bb = *(const float4*)&Ks[kk][tx*4];
        acc[0][0] += a.x*bb.x; acc[0][1] += a.x*bb.y; acc[0][2] += a.x*bb.z; acc[0][3] += a.x*bb.w;
        acc[1][0] += a.y*bb.x; acc[1][1] += a.y*bb.y; acc[1][2] += a.y*bb.z; acc[1][3] += a.y*bb.w;
        acc[2][0] += a.z*bb.x; acc[2][1] += a.z*bb.y; acc[2][2] += a.z*bb.z; acc[2][3] += a.z*bb.w;
        acc[3][0] += a.w*bb.x; acc[3][1] += a.w*bb.y; acc[3][2] += a.w*bb.z; acc[3][3] += a.w*bb.w;
    }

    int kbase = bk + tx*4;
    const int* mrow = mask + (size_t)b * S_;
    int m0 = mrow[kbase+0], m1 = mrow[kbase+1], m2 = mrow[kbase+2], m3 = mrow[kbase+3];
    #pragma unroll
    for (int i = 0; i < 4; i++) {
        int qi = bq + ty*4 + i;
        float4 o;
        o.x = (m0 == 0) ? -1e10f : acc[i][0] * 0.125f;
        o.y = (m1 == 0) ? -1e10f : acc[i][1] * 0.125f;
        o.z = (m2 == 0) ? -1e10f : acc[i][2] * 0.125f;
        o.w = (m3 == 0) ? -1e10f : acc[i][3] * 0.125f;
        *(float4*)&attn[(((size_t)bh * S_) + qi) * S_ + kbase] = o;
    }
}

// ============================================================================
// Softmax in place over rows of 1024.  One block (256 thr) per row.
// ============================================================================
__global__ void __launch_bounds__(256) softmax_kernel(float* __restrict__ attn)
{
    size_t row = blockIdx.x;
    float4* p = reinterpret_cast<float4*>(attn + row * S_);
    int tid = threadIdx.x, lane = tid & 31, wid = tid >> 5;
    __shared__ float red[8];

    float4 v = p[tid];
    float mx = fmaxf(fmaxf(v.x, v.y), fmaxf(v.z, v.w));
    #pragma unroll
    for (int o = 16; o > 0; o >>= 1) mx = fmaxf(mx, __shfl_xor_sync(0xffffffffu, mx, o));
    if (lane == 0) red[wid] = mx;
    __syncthreads();
    mx = red[0];
    #pragma unroll
    for (int i = 1; i < 8; i++) mx = fmaxf(mx, red[i]);
    __syncthreads();

    float e0 = __expf(v.x - mx), e1 = __expf(v.y - mx);
    float e2 = __expf(v.z - mx), e3 = __expf(v.w - mx);
    float s = e0 + e1 + e2 + e3;
    #pragma unroll
    for (int o = 16; o > 0; o >>= 1) s += __shfl_xor_sync(0xffffffffu, s, o);
    if (lane == 0) red[wid] = s;
    __syncthreads();
    float tot = red[0];
    #pragma unroll
    for (int i = 1; i < 8; i++) tot += red[i];
    float inv = 1.0f / tot;

    float4 o;
    o.x = e0 * inv; o.y = e1 * inv; o.z = e2 * inv; o.w = e3 * inv;
    p[tid] = o;
}

// ============================================================================
// ctx = attn @ V per (b,h): [1024,1024]@[1024,64] -> [1024,64], merged-head out.
// Tile: 64 q rows x 64 d cols (full HD), kTile=32.
// ============================================================================
__global__ void __launch_bounds__(256) ctx_kernel(
    const float* __restrict__ attn, const float* __restrict__ v,
    float* __restrict__ ctx)
{
    int bh = blockIdx.z;
    int b = bh / H_, h = bh % H_;
    const float* A = attn + (size_t)bh * S_ * S_;
    const float* V = v + (size_t)bh * S_ * HD_;
    int bq = blockIdx.x * 64;

    __shared__ float As[32][64];  // [k][q]
    __shared__ float Bs[32][64];  // [k][d]
    int tid = threadIdx.x;
    int tx = tid & 15, ty = tid >> 4;
    int lr = tid >> 2;            // 0..63 (A rows)
    int r2 = tid >> 3;            // 0..31 (V rows)
    int c2 = (tid & 7) * 8;       // V cols

    float acc[4][4] = {};
    for (int k0 = 0; k0 < S_; k0 += 32) {
        #pragma unroll
        for (int it = 0; it < 2; it++) {
            int c = (tid & 3) * 4 + it * 16;
            float4 av = *(const float4*)&A[(size_t)(bq + lr) * S_ + k0 + c];
            As[c+0][lr] = av.x; As[c+1][lr] = av.y; As[c+2][lr] = av.z; As[c+3][lr] = av.w;
        }
        float4 v0 = *(const float4*)&V[(size_t)(k0 + r2) * HD_ + c2];
        float4 v1 = *(const float4*)&V[(size_t)(k0 + r2) * HD_ + c2 + 4];
        *(float4*)&Bs[r2][c2]     = v0;
        *(float4*)&Bs[r2][c2 + 4] = v1;
        __syncthreads();
        #pragma unroll
        for (int kk = 0; kk < 32; kk++) {
            float4 a = *(const float4*)&As[kk][ty*4];
            float4 bb = *(const float4*)&Bs[kk][tx*4];
            acc[0][0] += a.x*bb.x; acc[0][1] += a.x*bb.y; acc[0][2] += a.x*bb.z; acc[0][3] += a.x*bb.w;
            acc[1][0] += a.y*bb.x; acc[1][1] += a.y*bb.y; acc[1][2] += a.y*bb.z; acc[1][3] += a.y*bb.w;
            acc[2][0] += a.z*bb.x; acc[2][1] += a.z*bb.y; acc[2][2] += a.z*bb.z; acc[2][3] += a.z*bb.w;
            acc[3][0] += a.w*bb.x; acc[3][1] += a.w*bb.y; acc[3][2] += a.w*bb.z; acc[3][3] += a.w*bb.w;
        }
        __syncthreads();
    }
    int db = tx*4;
    #pragma unroll
    for (int i = 0; i < 4; i++) {
        int qi = bq + ty*4 + i;
        float4 o; o.x = acc[i][0]; o.y = acc[i][1]; o.z = acc[i][2]; o.w = acc[i][3];
        *(float4*)&g_ctx[((size_t)b * S_ + qi) * D_ + h * HD_ + db] = o;
    }
    (void)ctx;
}

// ============================================================================
extern "C" void kernel_launch(void* const* d_in, const int* in_sizes, int n_in,
                              void* d_out, int out_size)
{
    const float* query = (const float*)d_in[0];
    const float* key_  = (const float*)d_in[1];
    const float* value = (const float*)d_in[2];
    const int*   mask  = (const int*)d_in[3];
    const float* Wq = (const float*)d_in[4];  const float* bq = (const float*)d_in[5];
    const float* Wk = (const float*)d_in[6];  const float* bk = (const float*)d_in[7];
    const float* Wv = (const float*)d_in[8];  const float* bv = (const float*)d_in[9];
    const float* Wo = (const float*)d_in[10]; const float* bo = (const float*)d_in[11];
    float* out = (float*)d_out;

    float *pq, *pk, *pv, *pctx, *pfb;
    cudaGetSymbolAddress((void**)&pq,   g_q);
    cudaGetSymbolAddress((void**)&pk,   g_k);
    cudaGetSymbolAddress((void**)&pv,   g_v);
    cudaGetSymbolAddress((void**)&pctx, g_ctx);
    cudaGetSymbolAddress((void**)&pfb,  g_attn_fb);

    const size_t OUT_E = (size_t)M_ * D_;                 // 4,194,304
    const size_t ATT_E = (size_t)B_ * H_ * S_ * S_;       // 67,108,864
    float* attn = ((size_t)out_size >= OUT_E + ATT_E) ? (out + OUT_E) : pfb;

    dim3 blk(256);
    dim3 gproj(M_ / 64, D_ / 64);
    proj_kernel<0><<<gproj, blk>>>(query, Wq, bq, pq);
    proj_kernel<0><<<gproj, blk>>>(key_,  Wk, bk, pk);
    proj_kernel<0><<<gproj, blk>>>(value, Wv, bv, pv);

    dim3 gsc(S_ / 64, S_ / 64, B_ * H_);
    scores_kernel<<<gsc, blk>>>(pq, pk, mask, attn);

    softmax_kernel<<<B_ * H_ * S_, 256>>>(attn);

    dim3 gctx(S_ / 64, 1, B_ * H_);
    ctx_kernel<<<gctx, blk>>>(attn, pv, pctx);

    proj_kernel<1><<<gproj, blk>>>(pctx, Wo, bo, out);
}

// round 2
// speedup vs baseline: 1.1489x; 1.1489x over previous
#include <cuda_runtime.h>
#include <cstdint>

#define B_  4
#define S_  1024
#define D_  1024
#define H_  16
#define HD_ 64
#define M_  (B_*S_)

// ---------------- scratch (static __device__, no allocation) ----------------
__device__ float g_q[(size_t)B_*H_*S_*HD_];     // [B,H,S,HD]
__device__ float g_k[(size_t)B_*H_*S_*HD_];
__device__ float g_v[(size_t)B_*H_*S_*HD_];
__device__ float g_ctx[(size_t)M_*D_];          // merged heads [B,S,D]
__device__ float g_attn_fb[(size_t)B_*H_*S_*S_];

// ============================================================================
// Dense GEMM: Y = X @ W^T + bias.  X [M,K] rm, W [N,K] rm.
// 128x128 tile, kTile=16, 256 threads, 8x8 micro-tile (split halves).
// MODE 0: head-split output [B,H,S,HD]; MODE 1: plain [M,N].
// ============================================================================
template<int MODE>
__global__ void __launch_bounds__(256) proj_kernel(
    const float* __restrict__ X, const float* __restrict__ W,
    const float* __restrict__ bias, float* __restrict__ Y)
{
    const int K = D_;
    __shared__ float As[16][132];   // [k][m]
    __shared__ float Bs[16][132];   // [k][n]
    int tid = threadIdx.x;
    int tx = tid & 15, ty = tid >> 4;
    int bm = blockIdx.x * 128, bn = blockIdx.y * 128;

    // gmem load mapping: 2 float4 per thread per operand
    int row0 = tid >> 2,         kc0 = (tid & 3) * 4;
    int row1 = (tid + 256) >> 2, kc1 = kc0;   // (i&3) same for i and i+256

    float acc[2][4][2][4] = {};
    float4 pa0, pa1, pb0, pb1;

    pa0 = *(const float4*)&X[(size_t)(bm + row0) * K + kc0];
    pa1 = *(const float4*)&X[(size_t)(bm + row1) * K + kc1];
    pb0 = *(const float4*)&W[(size_t)(bn + row0) * K + kc0];
    pb1 = *(const float4*)&W[(size_t)(bn + row1) * K + kc1];

    for (int k0 = 0; k0 < K; k0 += 16) {
        As[kc0+0][row0]=pa0.x; As[kc0+1][row0]=pa0.y; As[kc0+2][row0]=pa0.z; As[kc0+3][row0]=pa0.w;
        As[kc1+0][row1]=pa1.x; As[kc1+1][row1]=pa1.y; As[kc1+2][row1]=pa1.z; As[kc1+3][row1]=pa1.w;
        Bs[kc0+0][row0]=pb0.x; Bs[kc0+1][row0]=pb0.y; Bs[kc0+2][row0]=pb0.z; Bs[kc0+3][row0]=pb0.w;
        Bs[kc1+0][row1]=pb1.x; Bs[kc1+1][row1]=pb1.y; Bs[kc1+2][row1]=pb1.z; Bs[kc1+3][row1]=pb1.w;
        __syncthreads();
        if (k0 + 16 < K) {
            int kn = k0 + 16;
            pa0 = *(const float4*)&X[(size_t)(bm + row0) * K + kn + kc0];
            pa1 = *(const float4*)&X[(size_t)(bm + row1) * K + kn + kc1];
            pb0 = *(const float4*)&W[(size_t)(bn + row0) * K + kn + kc0];
            pb1 = *(const float4*)&W[(size_t)(bn + row1) * K + kn + kc1];
        }
        #pragma unroll
        for (int kk = 0; kk < 16; kk++) {
            float av[8], bv[8];
            *(float4*)&av[0] = *(const float4*)&As[kk][ty*4];
            *(float4*)&av[4] = *(const float4*)&As[kk][64 + ty*4];
            *(float4*)&bv[0] = *(const float4*)&Bs[kk][tx*4];
            *(float4*)&bv[4] = *(const float4*)&Bs[kk][64 + tx*4];
            #pragma unroll
            for (int ri = 0; ri < 2; ri++)
            #pragma unroll
            for (int i = 0; i < 4; i++)
            #pragma unroll
            for (int ci = 0; ci < 2; ci++)
            #pragma unroll
            for (int j = 0; j < 4; j++)
                acc[ri][i][ci][j] += av[ri*4+i] * bv[ci*4+j];
        }
        __syncthreads();
    }

    #pragma unroll
    for (int ci = 0; ci < 2; ci++) {
        int nb = bn + ci*64 + tx*4;
        float4 b4 = *(const float4*)&bias[nb];
        #pragma unroll
        for (int ri = 0; ri < 2; ri++)
        #pragma unroll
        for (int i = 0; i < 4; i++) {
            int m = bm + ri*64 + ty*4 + i;
            float4 o;
            o.x = acc[ri][i][ci][0] + b4.x; o.y = acc[ri][i][ci][1] + b4.y;
            o.z = acc[ri][i][ci][2] + b4.z; o.w = acc[ri][i][ci][3] + b4.w;
            if (MODE == 0) {
                int b = m >> 10, s = m & 1023;
                int h = nb >> 6, d = nb & 63;
                *(float4*)&Y[((((size_t)b*H_ + h)*S_) + s)*HD_ + d] = o;
            } else {
                *(float4*)&Y[(size_t)m*D_ + nb] = o;
            }
        }
    }
}

// ============================================================================
// Scores: per (b,h): S[q,k] = (Q·K) * 0.125, masked -> attn buffer.
// 128x128 tile, kTile=16 (K=64 -> 4 iters), 8x8 micro.
// ============================================================================
__global__ void __launch_bounds__(256) scores_kernel(
    const float* __restrict__ q, const float* __restrict__ kmat,
    const int* __restrict__ mask, float* __restrict__ attn)
{
    int bh = blockIdx.z;
    int b  = bh / H_;
    const float* Q  = q    + (size_t)bh * S_ * HD_;
    const float* Kp = kmat + (size_t)bh * S_ * HD_;
    int bq = blockIdx.x * 128, bk = blockIdx.y * 128;

    __shared__ float As[16][132];
    __shared__ float Bs[16][132];
    int tid = threadIdx.x;
    int tx = tid & 15, ty = tid >> 4;
    int row0 = tid >> 2,         kc0 = (tid & 3) * 4;
    int row1 = (tid + 256) >> 2, kc1 = kc0;

    float acc[2][4][2][4] = {};
    float4 pa0, pa1, pb0, pb1;
    pa0 = *(const float4*)&Q [(size_t)(bq + row0) * HD_ + kc0];
    pa1 = *(const float4*)&Q [(size_t)(bq + row1) * HD_ + kc1];
    pb0 = *(const float4*)&Kp[(size_t)(bk + row0) * HD_ + kc0];
    pb1 = *(const float4*)&Kp[(size_t)(bk + row1) * HD_ + kc1];

    for (int k0 = 0; k0 < HD_; k0 += 16) {
        As[kc0+0][row0]=pa0.x; As[kc0+1][row0]=pa0.y; As[kc0+2][row0]=pa0.z; As[kc0+3][row0]=pa0.w;
        As[kc1+0][row1]=pa1.x; As[kc1+1][row1]=pa1.y; As[kc1+2][row1]=pa1.z; As[kc1+3][row1]=pa1.w;
        Bs[kc0+0][row0]=pb0.x; Bs[kc0+1][row0]=pb0.y; Bs[kc0+2][row0]=pb0.z; Bs[kc0+3][row0]=pb0.w;
        Bs[kc1+0][row1]=pb1.x; Bs[kc1+1][row1]=pb1.y; Bs[kc1+2][row1]=pb1.z; Bs[kc1+3][row1]=pb1.w;
        __syncthreads();
        if (k0 + 16 < HD_) {
            int kn = k0 + 16;
            pa0 = *(const float4*)&Q [(size_t)(bq + row0) * HD_ + kn + kc0];
            pa1 = *(const float4*)&Q [(size_t)(bq + row1) * HD_ + kn + kc1];
            pb0 = *(const float4*)&Kp[(size_t)(bk + row0) * HD_ + kn + kc0];
            pb1 = *(const float4*)&Kp[(size_t)(bk + row1) * HD_ + kn + kc1];
        }
        #pragma unroll
        for (int kk = 0; kk < 16; kk++) {
            float av[8], bv[8];
            *(float4*)&av[0] = *(const float4*)&As[kk][ty*4];
            *(float4*)&av[4] = *(const float4*)&As[kk][64 + ty*4];
            *(float4*)&bv[0] = *(const float4*)&Bs[kk][tx*4];
            *(float4*)&bv[4] = *(const float4*)&Bs[kk][64 + tx*4];
            #pragma unroll
            for (int ri = 0; ri < 2; ri++)
            #pragma unroll
            for (int i = 0; i < 4; i++)
            #pragma unroll
            for (int ci = 0; ci < 2; ci++)
            #pragma unroll
            for (int j = 0; j < 4; j++)
                acc[ri][i][ci][j] += av[ri*4+i] * bv[ci*4+j];
        }
        __syncthreads();
    }

    const int* mrow = mask + (size_t)b * S_;
    #pragma unroll
    for (int ci = 0; ci < 2; ci++) {
        int kb = bk + ci*64 + tx*4;
        int m0 = mrow[kb+0], m1 = mrow[kb+1], m2 = mrow[kb+2], m3 = mrow[kb+3];
        #pragma unroll
        for (int ri = 0; ri < 2; ri++)
        #pragma unroll
        for (int i = 0; i < 4; i++) {
            int qi = bq + ri*64 + ty*4 + i;
            float4 o;
            o.x = (m0 == 0) ? -1e10f : acc[ri][i][ci][0] * 0.125f;
            o.y = (m1 == 0) ? -1e10f : acc[ri][i][ci][1] * 0.125f;
            o.z = (m2 == 0) ? -1e10f : acc[ri][i][ci][2] * 0.125f;
            o.w = (m3 == 0) ? -1e10f : acc[ri][i][ci][3] * 0.125f;
            *(float4*)&attn[(((size_t)bh * S_) + qi) * S_ + kb] = o;
        }
    }
}

// ============================================================================
// Softmax in place over rows of 1024.  One block (256 thr) per row.
// ============================================================================
__global__ void __launch_bounds__(256) softmax_kernel(float* __restrict__ attn)
{
    size_t row = blockIdx.x;
    float4* p = reinterpret_cast<float4*>(attn + row * S_);
    int tid = threadIdx.x, lane = tid & 31, wid = tid >> 5;
    __shared__ float red[8];

    float4 v = p[tid];
    float mx = fmaxf(fmaxf(v.x, v.y), fmaxf(v.z, v.w));
    #pragma unroll
    for (int o = 16; o > 0; o >>= 1) mx = fmaxf(mx, __shfl_xor_sync(0xffffffffu, mx, o));
    if (lane == 0) red[wid] = mx;
    __syncthreads();
    mx = red[0];
    #pragma unroll
    for (int i = 1; i < 8; i++) mx = fmaxf(mx, red[i]);
    __syncthreads();

    float e0 = __expf(v.x - mx), e1 = __expf(v.y - mx);
    float e2 = __expf(v.z - mx), e3 = __expf(v.w - mx);
    float s = e0 + e1 + e2 + e3;
    #pragma unroll
    for (int o = 16; o > 0; o >>= 1) s += __shfl_xor_sync(0xffffffffu, s, o);
    if (lane == 0) red[wid] = s;
    __syncthreads();
    float tot = red[0];
    #pragma unroll
    for (int i = 1; i < 8; i++) tot += red[i];
    float inv = 1.0f / tot;

    float4 o;
    o.x = e0 * inv; o.y = e1 * inv; o.z = e2 * inv; o.w = e3 * inv;
    p[tid] = o;
}

// ============================================================================
// ctx = attn @ V per (b,h): [1024,1024]@[1024,64].
// Tile 128q x 64d, 128 threads (16x8), 8x8 micro (cols split 0/32), kTile=32.
// ============================================================================
__global__ void __launch_bounds__(128) ctx_kernel(
    const float* __restrict__ attn, const float* __restrict__ v)
{
    int bh = blockIdx.z;
    int b = bh / H_, h = bh % H_;
    const float* A = attn + (size_t)bh * S_ * S_;
    const float* V = v + (size_t)bh * S_ * HD_;
    int bq = blockIdx.x * 128;

    __shared__ float As[32][132];  // [k][q]
    __shared__ float Vs[32][68];   // [k][d]
    int tid = threadIdx.x;
    int tx = tid & 7, ty = tid >> 3;

    // A: 128x32 = 1024 f4, 8 per thread. V: 32x64 = 512 f32 = 128 f4, wait 4/thread? 512/4=128 f4 / 128 thr = 1 each... need 32 rows x 16 f4 = 512 f4 -> 4 per thread.
    int arow[8], akc[8];
    #pragma unroll
    for (int t = 0; t < 8; t++) { int i = tid + t*128; arow[t] = i >> 3; akc[t] = (i & 7) * 4; }
    int vrow[4], vc[4];
    #pragma unroll
    for (int t = 0; t < 4; t++) { int i = tid + t*128; vrow[t] = i >> 4; vc[t] = (i & 15) * 4; }

    float acc[2][4][2][4] = {};
    float4 pa[8], pv[4];
    #pragma unroll
    for (int t = 0; t < 8; t++) pa[t] = *(const float4*)&A[(size_t)(bq + arow[t]) * S_ + akc[t]];
    #pragma unroll
    for (int t = 0; t < 4; t++) pv[t] = *(const float4*)&V[(size_t)vrow[t] * HD_ + vc[t]];

    for (int k0 = 0; k0 < S_; k0 += 32) {
        #pragma unroll
        for (int t = 0; t < 8; t++) {
            As[akc[t]+0][arow[t]] = pa[t].x; As[akc[t]+1][arow[t]] = pa[t].y;
            As[akc[t]+2][arow[t]] = pa[t].z; As[akc[t]+3][arow[t]] = pa[t].w;
        }
        #pragma unroll
        for (int t = 0; t < 4; t++) *(float4*)&Vs[vrow[t]][vc[t]] = pv[t];
        __syncthreads();
        if (k0 + 32 < S_) {
            int kn = k0 + 32;
            #pragma unroll
            for (int t = 0; t < 8; t++) pa[t] = *(const float4*)&A[(size_t)(bq + arow[t]) * S_ + kn + akc[t]];
            #pragma unroll
            for (int t = 0; t < 4; t++) pv[t] = *(const float4*)&V[(size_t)(kn + vrow[t]) * HD_ + vc[t]];
        }
        #pragma unroll
        for (int kk = 0; kk < 32; kk++) {
            float av[8], bv[8];
            *(float4*)&av[0] = *(const float4*)&As[kk][ty*4];
            *(float4*)&av[4] = *(const float4*)&As[kk][64 + ty*4];
            *(float4*)&bv[0] = *(const float4*)&Vs[kk][tx*4];
            *(float4*)&bv[4] = *(const float4*)&Vs[kk][32 + tx*4];
            #pragma unroll
            for (int ri = 0; ri < 2; ri++)
            #pragma unroll
            for (int i = 0; i < 4; i++)
            #pragma unroll
            for (int ci = 0; ci < 2; ci++)
            #pragma unroll
            for (int j = 0; j < 4; j++)
                acc[ri][i][ci][j] += av[ri*4+i] * bv[ci*4+j];
        }
        __syncthreads();
    }

    #pragma unroll
    for (int ci = 0; ci < 2; ci++) {
        int d = ci*32 + tx*4;
        #pragma unroll
        for (int ri = 0; ri < 2; ri++)
        #pragma unroll
        for (int i = 0; i < 4; i++) {
            int qi = bq + ri*64 + ty*4 + i;
            float4 o;
            o.x = acc[ri][i][ci][0]; o.y = acc[ri][i][ci][1];
            o.z = acc[ri][i][ci][2]; o.w = acc[ri][i][ci][3];
            *(float4*)&g_ctx[((size_t)b * S_ + qi) * D_ + h * HD_ + d] = o;
        }
    }
}

// ============================================================================
extern "C" void kernel_launch(void* const* d_in, const int* in_sizes, int n_in,
                              void* d_out, int out_size)
{
    const float* query = (const float*)d_in[0];
    const float* key_  = (const float*)d_in[1];
    const float* value = (const float*)d_in[2];
    const int*   mask  = (const int*)d_in[3];
    const float* Wq = (const float*)d_in[4];  const float* bq = (const float*)d_in[5];
    const float* Wk = (const float*)d_in[6];  const float* bk = (const float*)d_in[7];
    const float* Wv = (const float*)d_in[8];  const float* bv = (const float*)d_in[9];
    const float* Wo = (const float*)d_in[10]; const float* bo = (const float*)d_in[11];
    float* out = (float*)d_out;

    float *pq, *pk, *pv, *pctx, *pfb;
    cudaGetSymbolAddress((void**)&pq,   g_q);
    cudaGetSymbolAddress((void**)&pk,   g_k);
    cudaGetSymbolAddress((void**)&pv,   g_v);
    cudaGetSymbolAddress((void**)&pctx, g_ctx);
    cudaGetSymbolAddress((void**)&pfb,  g_attn_fb);

    const size_t OUT_E = (size_t)M_ * D_;
    const size_t ATT_E = (size_t)B_ * H_ * S_ * S_;
    float* attn = ((size_t)out_size >= OUT_E + ATT_E) ? (out + OUT_E) : pfb;

    dim3 blk(256);
    dim3 gproj(M_ / 128, D_ / 128);
    proj_kernel<0><<<gproj, blk>>>(query, Wq, bq, pq);
    proj_kernel<0><<<gproj, blk>>>(key_,  Wk, bk, pk);
    proj_kernel<0><<<gproj, blk>>>(value, Wv, bv, pv);

    dim3 gsc(S_ / 128, S_ / 128, B_ * H_);
    scores_kernel<<<gsc, blk>>>(pq, pk, mask, attn);

    softmax_kernel<<<B_ * H_ * S_, 256>>>(attn);

    dim3 gctx(S_ / 128, 1, B_ * H_);
    ctx_kernel<<<gctx, 128>>>(attn, pv);

    proj_kernel<1><<<gproj, blk>>>(pctx, Wo, bo, out);
}

// round 4
// speedup vs baseline: 1.7470x; 1.5206x over previous
#include <cuda_runtime.h>
#include <cuda_bf16.h>
#include <cstdint>

#define B_  4
#define S_  1024
#define D_  1024
#define H_  16
#define HD_ 64
#define M_  (B_*S_)

// ---------------- scratch (static __device__, no allocation) ----------------
__device__ float g_q[(size_t)B_*H_*S_*HD_];
__device__ float g_k[(size_t)B_*H_*S_*HD_];
__device__ float g_v[(size_t)B_*H_*S_*HD_];
__device__ float g_ctx[(size_t)M_*D_];
__device__ float g_attn_fb[(size_t)B_*H_*S_*S_];
__device__ __nv_bfloat16 g_xhi[(size_t)M_*D_];
__device__ __nv_bfloat16 g_xlo[(size_t)M_*D_];
__device__ __nv_bfloat16 g_whi[(size_t)D_*D_];
__device__ __nv_bfloat16 g_wlo[(size_t)D_*D_];

// ================= arch-neutral PTX helpers (sm_80-era only) ================
__device__ __forceinline__ uint32_t smem_u32(const void* p) {
    uint32_t a;
    asm("{ .reg .u64 t; cvta.to.shared.u64 t, %1; cvt.u32.u64 %0, t; }" : "=r"(a) : "l"(p));
    return a;
}
__device__ __forceinline__ void cp_async16(uint32_t sdst, const void* gsrc) {
    asm volatile("cp.async.cg.shared.global [%0], [%1], 16;" :: "r"(sdst), "l"(gsrc) : "memory");
}
__device__ __forceinline__ void cp_commit() {
    asm volatile("cp.async.commit_group;" ::: "memory");
}
template<int N>
__device__ __forceinline__ void cp_wait() {
    asm volatile("cp.async.wait_group %0;" :: "n"(N) : "memory");
}
__device__ __forceinline__ void ldm_x4(uint32_t a, uint32_t& r0, uint32_t& r1,
                                       uint32_t& r2, uint32_t& r3) {
    asm volatile("ldmatrix.sync.aligned.m8n8.x4.shared.b16 {%0,%1,%2,%3}, [%4];"
        : "=r"(r0), "=r"(r1), "=r"(r2), "=r"(r3) : "r"(a));
}
__device__ __forceinline__ void mma_bf16(float* d, const uint32_t* a, const uint32_t* b) {
    asm volatile("mma.sync.aligned.m16n8k16.row.col.f32.bf16.bf16.f32 "
        "{%0,%1,%2,%3}, {%4,%5,%6,%7}, {%8,%9}, {%0,%1,%2,%3};"
        : "+f"(d[0]), "+f"(d[1]), "+f"(d[2]), "+f"(d[3])
        : "r"(a[0]), "r"(a[1]), "r"(a[2]), "r"(a[3]), "r"(b[0]), "r"(b[1]));
}

// ===================== fp32 -> bf16 hi/lo split =============================
__global__ void __launch_bounds__(256) split_kernel(
    const float* __restrict__ x, __nv_bfloat16* __restrict__ hi,
    __nv_bfloat16* __restrict__ lo, int n4)
{
    int i = blockIdx.x * 256 + threadIdx.x;
    if (i >= n4) return;
    float4 v = ((const float4*)x)[i];
    __nv_bfloat16 h0 = __float2bfloat16(v.x), h1 = __float2bfloat16(v.y);
    __nv_bfloat16 h2 = __float2bfloat16(v.z), h3 = __float2bfloat16(v.w);
    __nv_bfloat16 l0 = __float2bfloat16(v.x - __bfloat162float(h0));
    __nv_bfloat16 l1 = __float2bfloat16(v.y - __bfloat162float(h1));
    __nv_bfloat16 l2 = __float2bfloat16(v.z - __bfloat162float(h2));
    __nv_bfloat16 l3 = __float2bfloat16(v.w - __bfloat162float(h3));
    __nv_bfloat162 hp0, hp1, lp0, lp1;
    hp0.x = h0; hp0.y = h1; hp1.x = h2; hp1.y = h3;
    lp0.x = l0; lp0.y = l1; lp1.x = l2; lp1.y = l3;
    uint2 hv, lv;
    hv.x = *(uint32_t*)&hp0; hv.y = *(uint32_t*)&hp1;
    lv.x = *(uint32_t*)&lp0; lv.y = *(uint32_t*)&lp1;
    ((uint2*)hi)[i] = hv;
    ((uint2*)lo)[i] = lv;
}

// ============================================================================
// mma.sync GEMM: Y = X @ W^T + bias via split-bf16 (hi*hi + hi*lo + lo*hi).
// CTA tile 128x128, kChunk=32, 256 thr (8 warps, warp tile 32x64).
// Double-buffered cp.async smem. MODE 0: head-split out; MODE 1: plain [M,N].
// ============================================================================
#define LDK   40                       // padded row length (bf16 elems)
#define MAT_B (128 * LDK * 2)          // 10240 bytes per matrix tile
#define BUF_B (4 * MAT_B)              // Ah, Al, Bh, Bl
#define PROJ_SMEM (2 * BUF_B)          // 81920

template<int MODE>
__global__ void __launch_bounds__(256) mma_proj(
    const __nv_bfloat16* __restrict__ Xhi, const __nv_bfloat16* __restrict__ Xlo,
    const __nv_bfloat16* __restrict__ Whi, const __nv_bfloat16* __restrict__ Wlo,
    const float* __restrict__ bias, float* __restrict__ Y)
{
    extern __shared__ char smem[];
    const int K = D_;
    int tid = threadIdx.x, wid = tid >> 5, lane = tid & 31;
    int bm = blockIdx.x * 128, bn = blockIdx.y * 128;
    int warp_m = (wid & 3) * 32, warp_n = (wid >> 2) * 64;

    uint32_t sbase = smem_u32(smem);

    // loader mapping: row = tid>>1, col half = (tid&1)*16, two 16B per matrix
    int lrow = tid >> 1, lcol = (tid & 1) * 16;
    const __nv_bfloat16* gA_h = Xhi + (size_t)(bm + lrow) * K + lcol;
    const __nv_bfloat16* gA_l = Xlo + (size_t)(bm + lrow) * K + lcol;
    const __nv_bfloat16* gB_h = Whi + (size_t)(bn + lrow) * K + lcol;
    const __nv_bfloat16* gB_l = Wlo + (size_t)(bn + lrow) * K + lcol;
    uint32_t soff = (uint32_t)(lrow * LDK + lcol) * 2;

    auto issue_chunk = [&](int c, int buf) {
        uint32_t base = sbase + buf * BUF_B;
        int k0 = c * 32;
        #pragma unroll
        for (int h = 0; h < 2; h++) {     // two 16B (8-elem) pieces
            uint32_t so = soff + h * 16;
            int go = k0 + h * 8;
            cp_async16(base + 0*MAT_B + so, gA_h + go);
            cp_async16(base + 1*MAT_B + so, gA_l + go);
            cp_async16(base + 2*MAT_B + so, gB_h + go);
            cp_async16(base + 3*MAT_B + so, gB_l + go);
        }
        cp_commit();
    };

    float acc[2][8][4];
    #pragma unroll
    for (int mf = 0; mf < 2; mf++)
        #pragma unroll
        for (int nf = 0; nf < 8; nf++)
            #pragma unroll
            for (int r = 0; r < 4; r++) acc[mf][nf][r] = 0.f;

    const int NCH = K / 32;
    issue_chunk(0, 0);
    int buf = 0;

    // ldmatrix address components (within a matrix tile)
    uint32_t a_off = (uint32_t)((warp_m + (lane & 15)) * LDK + (lane >> 4) * 8) * 2;
    uint32_t b_off = (uint32_t)((warp_n + ((lane >> 4) * 8) + (lane & 7)) * LDK
                                + (((lane >> 3) & 1) * 8)) * 2;

    for (int c = 0; c < NCH; c++) {
        if (c + 1 < NCH) { issue_chunk(c + 1, buf ^ 1); cp_wait<1>(); }
        else cp_wait<0>();
        __syncthreads();

        uint32_t base = sbase + buf * BUF_B;
        #pragma unroll
        for (int ks = 0; ks < 2; ks++) {
            uint32_t kso = (uint32_t)(ks * 16) * 2;
            uint32_t ah[2][4], al[2][4], bh[8][2], bl[8][2];
            #pragma unroll
            for (int mf = 0; mf < 2; mf++) {
                uint32_t ao = a_off + (uint32_t)(mf * 16 * LDK) * 2 + kso;
                ldm_x4(base + 0*MAT_B + ao, ah[mf][0], ah[mf][1], ah[mf][2], ah[mf][3]);
                ldm_x4(base + 1*MAT_B + ao, al[mf][0], al[mf][1], al[mf][2], al[mf][3]);
            }
            #pragma unroll
            for (int bg = 0; bg < 4; bg++) {
                uint32_t bo = b_off + (uint32_t)(bg * 16 * LDK) * 2 + kso;
                ldm_x4(base + 2*MAT_B + bo, bh[bg*2][0], bh[bg*2][1], bh[bg*2+1][0], bh[bg*2+1][1]);
                ldm_x4(base + 3*MAT_B + bo, bl[bg*2][0], bl[bg*2][1], bl[bg*2+1][0], bl[bg*2+1][1]);
            }
            #pragma unroll
            for (int mf = 0; mf < 2; mf++)
                #pragma unroll
                for (int nf = 0; nf < 8; nf++) {
                    mma_bf16(acc[mf][nf], ah[mf], bh[nf]);
                    mma_bf16(acc[mf][nf], ah[mf], bl[nf]);
                    mma_bf16(acc[mf][nf], al[mf], bh[nf]);
                }
        }
        __syncthreads();
        buf ^= 1;
    }

    // Epilogue: D frags -> gmem (+bias).  d0,d1 @ (m, n..n+1); d2,d3 @ (m+8).
    int g = lane >> 2;
    #pragma unroll
    for (int nf = 0; nf < 8; nf++) {
        int n = bn + warp_n + nf * 8 + (lane & 3) * 2;
        float b0 = bias[n], b1 = bias[n + 1];
        #pragma unroll
        for (int mf = 0; mf < 2; mf++) {
            int m = bm + warp_m + mf * 16 + g;
            float2 o0, o1;
            o0.x = acc[mf][nf][0] + b0; o0.y = acc[mf][nf][1] + b1;
            o1.x = acc[mf][nf][2] + b0; o1.y = acc[mf][nf][3] + b1;
            if (MODE == 0) {
                int bb = m >> 10, s = m & 1023;
                int h = n >> 6, d = n & 63;
                size_t rb = (((size_t)bb * H_ + h) * S_);
                *(float2*)&Y[(rb + s) * HD_ + d] = o0;
                *(float2*)&Y[(rb + s + 8) * HD_ + d] = o1;
            } else {
                *(float2*)&Y[(size_t)m * D_ + n] = o0;
                *(float2*)&Y[(size_t)(m + 8) * D_ + n] = o1;
            }
        }
    }
}

// ============================================================================
// Scores (SIMT, unchanged from best-passing R2 kernel)
// ============================================================================
__global__ void __launch_bounds__(256) scores_kernel(
    const float* __restrict__ q, const float* __restrict__ kmat,
    const int* __restrict__ mask, float* __restrict__ attn)
{
    int bh = blockIdx.z;
    int b  = bh / H_;
    const float* Q  = q    + (size_t)bh * S_ * HD_;
    const float* Kp = kmat + (size_t)bh * S_ * HD_;
    int bq = blockIdx.x * 128, bk = blockIdx.y * 128;

    __shared__ float As[16][132];
    __shared__ float Bs[16][132];
    int tid = threadIdx.x;
    int tx = tid & 15, ty = tid >> 4;
    int row0 = tid >> 2,         kc0 = (tid & 3) * 4;
    int row1 = (tid + 256) >> 2, kc1 = kc0;

    float acc[2][4][2][4] = {};
    float4 pa0, pa1, pb0, pb1;
    pa0 = *(const float4*)&Q [(size_t)(bq + row0) * HD_ + kc0];
    pa1 = *(const float4*)&Q [(size_t)(bq + row1) * HD_ + kc1];
    pb0 = *(const float4*)&Kp[(size_t)(bk + row0) * HD_ + kc0];
    pb1 = *(const float4*)&Kp[(size_t)(bk + row1) * HD_ + kc1];

    for (int k0 = 0; k0 < HD_; k0 += 16) {
        As[kc0+0][row0]=pa0.x; As[kc0+1][row0]=pa0.y; As[kc0+2][row0]=pa0.z; As[kc0+3][row0]=pa0.w;
        As[kc1+0][row1]=pa1.x; As[kc1+1][row1]=pa1.y; As[kc1+2][row1]=pa1.z; As[kc1+3][row1]=pa1.w;
        Bs[kc0+0][row0]=pb0.x; Bs[kc0+1][row0]=pb0.y; Bs[kc0+2][row0]=pb0.z; Bs[kc0+3][row0]=pb0.w;
        Bs[kc1+0][row1]=pb1.x; Bs[kc1+1][row1]=pb1.y; Bs[kc1+2][row1]=pb1.z; Bs[kc1+3][row1]=pb1.w;
        __syncthreads();
        if (k0 + 16 < HD_) {
            int kn = k0 + 16;
            pa0 = *(const float4*)&Q [(size_t)(bq + row0) * HD_ + kn + kc0];
            pa1 = *(const float4*)&Q [(size_t)(bq + row1) * HD_ + kn + kc1];
            pb0 = *(const float4*)&Kp[(size_t)(bk + row0) * HD_ + kn + kc0];
            pb1 = *(const float4*)&Kp[(size_t)(bk + row1) * HD_ + kn + kc1];
        }
        #pragma unroll
        for (int kk = 0; kk < 16; kk++) {
            float av[8], bv[8];
            *(float4*)&av[0] = *(const float4*)&As[kk][ty*4];
            *(float4*)&av[4] = *(const float4*)&As[kk][64 + ty*4];
            *(float4*)&bv[0] = *(const float4*)&Bs[kk][tx*4];
            *(float4*)&bv[4] = *(const float4*)&Bs[kk][64 + tx*4];
            #pragma unroll
            for (int ri = 0; ri < 2; ri++)
            #pragma unroll
            for (int i = 0; i < 4; i++)
            #pragma unroll
            for (int ci = 0; ci < 2; ci++)
            #pragma unroll
            for (int j = 0; j < 4; j++)
                acc[ri][i][ci][j] += av[ri*4+i] * bv[ci*4+j];
        }
        __syncthreads();
    }

    const int* mrow = mask + (size_t)b * S_;
    #pragma unroll
    for (int ci = 0; ci < 2; ci++) {
        int kb = bk + ci*64 + tx*4;
        int m0 = mrow[kb+0], m1 = mrow[kb+1], m2 = mrow[kb+2], m3 = mrow[kb+3];
        #pragma unroll
        for (int ri = 0; ri < 2; ri++)
        #pragma unroll
        for (int i = 0; i < 4; i++) {
            int qi = bq + ri*64 + ty*4 + i;
            float4 o;
            o.x = (m0 == 0) ? -1e10f : acc[ri][i][ci][0] * 0.125f;
            o.y = (m1 == 0) ? -1e10f : acc[ri][i][ci][1] * 0.125f;
            o.z = (m2 == 0) ? -1e10f : acc[ri][i][ci][2] * 0.125f;
            o.w = (m3 == 0) ? -1e10f : acc[ri][i][ci][3] * 0.125f;
            *(float4*)&attn[(((size_t)bh * S_) + qi) * S_ + kb] = o;
        }
    }
}

// ============================================================================
// Softmax (unchanged)
// ============================================================================
__global__ void __launch_bounds__(256) softmax_kernel(float* __restrict__ attn)
{
    size_t row = blockIdx.x;
    float4* p = reinterpret_cast<float4*>(attn + row * S_);
    int tid = threadIdx.x, lane = tid & 31, wid = tid >> 5;
    __shared__ float red[8];

    float4 v = p[tid];
    float mx = fmaxf(fmaxf(v.x, v.y), fmaxf(v.z, v.w));
    #pragma unroll
    for (int o = 16; o > 0; o >>= 1) mx = fmaxf(mx, __shfl_xor_sync(0xffffffffu, mx, o));
    if (lane == 0) red[wid] = mx;
    __syncthreads();
    mx = red[0];
    #pragma unroll
    for (int i = 1; i < 8; i++) mx = fmaxf(mx, red[i]);
    __syncthreads();

    float e0 = __expf(v.x - mx), e1 = __expf(v.y - mx);
    float e2 = __expf(v.z - mx), e3 = __expf(v.w - mx);
    float s = e0 + e1 + e2 + e3;
    #pragma unroll
    for (int o = 16; o > 0; o >>= 1) s += __shfl_xor_sync(0xffffffffu, s, o);
    if (lane == 0) red[wid] = s;
    __syncthreads();
    float tot = red[0];
    #pragma unroll
    for (int i = 1; i < 8; i++) tot += red[i];
    float inv = 1.0f / tot;

    float4 o;
    o.x = e0 * inv; o.y = e1 * inv; o.z = e2 * inv; o.w = e3 * inv;
    p[tid] = o;
}

// ============================================================================
// ctx = attn @ V (SIMT, unchanged)
// ============================================================================
__global__ void __launch_bounds__(128) ctx_kernel(
    const float* __restrict__ attn, const float* __restrict__ v)
{
    int bh = blockIdx.z;
    int b = bh / H_, h = bh % H_;
    const float* A = attn + (size_t)bh * S_ * S_;
    const float* V = v + (size_t)bh * S_ * HD_;
    int bq = blockIdx.x * 128;

    __shared__ float As[32][132];
    __shared__ float Vs[32][68];
    int tid = threadIdx.x;
    int tx = tid & 7, ty = tid >> 3;

    int arow[8], akc[8];
    #pragma unroll
    for (int t = 0; t < 8; t++) { int i = tid + t*128; arow[t] = i >> 3; akc[t] = (i & 7) * 4; }
    int vrow[4], vc[4];
    #pragma unroll
    for (int t = 0; t < 4; t++) { int i = tid + t*128; vrow[t] = i >> 4; vc[t] = (i & 15) * 4; }

    float acc[2][4][2][4] = {};
    float4 pa[8], pv[4];
    #pragma unroll
    for (int t = 0; t < 8; t++) pa[t] = *(const float4*)&A[(size_t)(bq + arow[t]) * S_ + akc[t]];
    #pragma unroll
    for (int t = 0; t < 4; t++) pv[t] = *(const float4*)&V[(size_t)vrow[t] * HD_ + vc[t]];

    for (int k0 = 0; k0 < S_; k0 += 32) {
        #pragma unroll
        for (int t = 0; t < 8; t++) {
            As[akc[t]+0][arow[t]] = pa[t].x; As[akc[t]+1][arow[t]] = pa[t].y;
            As[akc[t]+2][arow[t]] = pa[t].z; As[akc[t]+3][arow[t]] = pa[t].w;
        }
        #pragma unroll
        for (int t = 0; t < 4; t++) *(float4*)&Vs[vrow[t]][vc[t]] = pv[t];
        __syncthreads();
        if (k0 + 32 < S_) {
            int kn = k0 + 32;
            #pragma unroll
            for (int t = 0; t < 8; t++) pa[t] = *(const float4*)&A[(size_t)(bq + arow[t]) * S_ + kn + akc[t]];
            #pragma unroll
            for (int t = 0; t < 4; t++) pv[t] = *(const float4*)&V[(size_t)(kn + vrow[t]) * HD_ + vc[t]];
        }
        #pragma unroll
        for (int kk = 0; kk < 32; kk++) {
            float av[8], bv[8];
            *(float4*)&av[0] = *(const float4*)&As[kk][ty*4];
            *(float4*)&av[4] = *(const float4*)&As[kk][64 + ty*4];
            *(float4*)&bv[0] = *(const float4*)&Vs[kk][tx*4];
            *(float4*)&bv[4] = *(const float4*)&Vs[kk][32 + tx*4];
            #pragma unroll
            for (int ri = 0; ri < 2; ri++)
            #pragma unroll
            for (int i = 0; i < 4; i++)
            #pragma unroll
            for (int ci = 0; ci < 2; ci++)
            #pragma unroll
            for (int j = 0; j < 4; j++)
                acc[ri][i][ci][j] += av[ri*4+i] * bv[ci*4+j];
        }
        __syncthreads();
    }

    #pragma unroll
    for (int ci = 0; ci < 2; ci++) {
        int d = ci*32 + tx*4;
        #pragma unroll
        for (int ri = 0; ri < 2; ri++)
        #pragma unroll
        for (int i = 0; i < 4; i++) {
            int qi = bq + ri*64 + ty*4 + i;
            float4 o;
            o.x = acc[ri][i][ci][0]; o.y = acc[ri][i][ci][1];
            o.z = acc[ri][i][ci][2]; o.w = acc[ri][i][ci][3];
            *(float4*)&g_ctx[((size_t)b * S_ + qi) * D_ + h * HD_ + d] = o;
        }
    }
}

// ============================================================================
extern "C" void kernel_launch(void* const* d_in, const int* in_sizes, int n_in,
                              void* d_out, int out_size)
{
    const float* query = (const float*)d_in[0];
    const float* key_  = (const float*)d_in[1];
    const float* value = (const float*)d_in[2];
    const int*   mask  = (const int*)d_in[3];
    const float* Wq = (const float*)d_in[4];  const float* bq = (const float*)d_in[5];
    const float* Wk = (const float*)d_in[6];  const float* bk = (const float*)d_in[7];
    const float* Wv = (const float*)d_in[8];  const float* bv = (const float*)d_in[9];
    const float* Wo = (const float*)d_in[10]; const float* bo = (const float*)d_in[11];
    float* out = (float*)d_out;

    float *pq, *pk, *pv, *pctx, *pfb;
    __nv_bfloat16 *pxh, *pxl, *pwh, *pwl;
    cudaGetSymbolAddress((void**)&pq,   g_q);
    cudaGetSymbolAddress((void**)&pk,   g_k);
    cudaGetSymbolAddress((void**)&pv,   g_v);
    cudaGetSymbolAddress((void**)&pctx, g_ctx);
    cudaGetSymbolAddress((void**)&pfb,  g_attn_fb);
    cudaGetSymbolAddress((void**)&pxh,  g_xhi);
    cudaGetSymbolAddress((void**)&pxl,  g_xlo);
    cudaGetSymbolAddress((void**)&pwh,  g_whi);
    cudaGetSymbolAddress((void**)&pwl,  g_wlo);

    static bool attr_set = false;
    if (!attr_set) {
        cudaFuncSetAttribute(mma_proj<0>, cudaFuncAttributeMaxDynamicSharedMemorySize, PROJ_SMEM);
        cudaFuncSetAttribute(mma_proj<1>, cudaFuncAttributeMaxDynamicSharedMemorySize, PROJ_SMEM);
        attr_set = true;
    }

    const size_t OUT_E = (size_t)M_ * D_;
    const size_t ATT_E = (size_t)B_ * H_ * S_ * S_;
    float* attn = ((size_t)out_size >= OUT_E + ATT_E) ? (out + OUT_E) : pfb;

    const int NX4 = M_ * D_ / 4;
    const int NW4 = D_ * D_ / 4;
    dim3 gx((NX4 + 255) / 256), gw((NW4 + 255) / 256);
    dim3 gproj(M_ / 128, D_ / 128);

    // Q projection
    split_kernel<<<gx, 256>>>(query, pxh, pxl, NX4);
    split_kernel<<<gw, 256>>>(Wq, pwh, pwl, NW4);
    mma_proj<0><<<gproj, 256, PROJ_SMEM>>>(pxh, pxl, pwh, pwl, bq, pq);
    // K projection
    split_kernel<<<gx, 256>>>(key_, pxh, pxl, NX4);
    split_kernel<<<gw, 256>>>(Wk, pwh, pwl, NW4);
    mma_proj<0><<<gproj, 256, PROJ_SMEM>>>(pxh, pxl, pwh, pwl, bk, pk);
    // V projection
    split_kernel<<<gx, 256>>>(value, pxh, pxl, NX4);
    split_kernel<<<gw, 256>>>(Wv, pwh, pwl, NW4);
    mma_proj<0><<<gproj, 256, PROJ_SMEM>>>(pxh, pxl, pwh, pwl, bv, pv);

    dim3 gsc(S_ / 128, S_ / 128, B_ * H_);
    scores_kernel<<<gsc, 256>>>(pq, pk, mask, attn);

    softmax_kernel<<<B_ * H_ * S_, 256>>>(attn);

    dim3 gctx(S_ / 128, 1, B_ * H_);
    ctx_kernel<<<gctx, 128>>>(attn, pv);

    // Output projection
    split_kernel<<<gx, 256>>>(pctx, pxh, pxl, NX4);
    split_kernel<<<gw, 256>>>(Wo, pwh, pwl, NW4);
    mma_proj<1><<<gproj, 256, PROJ_SMEM>>>(pxh, pxl, pwh, pwl, bo, out);
}

// round 6
// speedup vs baseline: 2.3251x; 1.3310x over previous
#include <cuda_runtime.h>
#include <cuda_bf16.h>
#include <cstdint>

#define B_  4
#define S_  1024
#define D_  1024
#define H_  16
#define HD_ 64
#define M_  (B_*S_)

// ---------------- scratch (static __device__, no allocation) ----------------
__device__ float g_ctx[(size_t)M_*D_];
__device__ float g_attn_fb[(size_t)B_*H_*S_*S_];
__device__ __nv_bfloat16 g_xhi[(size_t)M_*D_];
__device__ __nv_bfloat16 g_xlo[(size_t)M_*D_];
__device__ __nv_bfloat16 g_whi[(size_t)D_*D_];
__device__ __nv_bfloat16 g_wlo[(size_t)D_*D_];
__device__ __nv_bfloat16 g_qh[(size_t)B_*H_*S_*HD_];
__device__ __nv_bfloat16 g_ql[(size_t)B_*H_*S_*HD_];
__device__ __nv_bfloat16 g_kh[(size_t)B_*H_*S_*HD_];
__device__ __nv_bfloat16 g_kl[(size_t)B_*H_*S_*HD_];
__device__ __nv_bfloat16 g_vh[(size_t)B_*H_*S_*HD_];
__device__ __nv_bfloat16 g_vl[(size_t)B_*H_*S_*HD_];

// ================= arch-neutral PTX helpers (sm_80-era only) ================
__device__ __forceinline__ uint32_t smem_u32(const void* p) {
    uint32_t a;
    asm("{ .reg .u64 t; cvta.to.shared.u64 t, %1; cvt.u32.u64 %0, t; }" : "=r"(a) : "l"(p));
    return a;
}
__device__ __forceinline__ void cp_async16(uint32_t sdst, const void* gsrc) {
    asm volatile("cp.async.cg.shared.global [%0], [%1], 16;" :: "r"(sdst), "l"(gsrc) : "memory");
}
__device__ __forceinline__ void cp_commit() {
    asm volatile("cp.async.commit_group;" ::: "memory");
}
template<int N>
__device__ __forceinline__ void cp_wait() {
    asm volatile("cp.async.wait_group %0;" :: "n"(N) : "memory");
}
__device__ __forceinline__ void ldm_x4(uint32_t a, uint32_t& r0, uint32_t& r1,
                                       uint32_t& r2, uint32_t& r3) {
    asm volatile("ldmatrix.sync.aligned.m8n8.x4.shared.b16 {%0,%1,%2,%3}, [%4];"
        : "=r"(r0), "=r"(r1), "=r"(r2), "=r"(r3) : "r"(a));
}
__device__ __forceinline__ void ldm_x4_t(uint32_t a, uint32_t& r0, uint32_t& r1,
                                         uint32_t& r2, uint32_t& r3) {
    asm volatile("ldmatrix.sync.aligned.m8n8.x4.trans.shared.b16 {%0,%1,%2,%3}, [%4];"
        : "=r"(r0), "=r"(r1), "=r"(r2), "=r"(r3) : "r"(a));
}
__device__ __forceinline__ void mma_bf16(float* d, const uint32_t* a, const uint32_t* b) {
    asm volatile("mma.sync.aligned.m16n8k16.row.col.f32.bf16.bf16.f32 "
        "{%0,%1,%2,%3}, {%4,%5,%6,%7}, {%8,%9}, {%0,%1,%2,%3};"
        : "+f"(d[0]), "+f"(d[1]), "+f"(d[2]), "+f"(d[3])
        : "r"(a[0]), "r"(a[1]), "r"(a[2]), "r"(a[3]), "r"(b[0]), "r"(b[1]));
}
__device__ __forceinline__ void split2(float a, float b, uint32_t& hi, uint32_t& lo) {
    __nv_bfloat16 ha = __float2bfloat16(a), hb = __float2bfloat16(b);
    __nv_bfloat162 hp; hp.x = ha; hp.y = hb;
    __nv_bfloat162 lp;
    lp.x = __float2bfloat16(a - __bfloat162float(ha));
    lp.y = __float2bfloat16(b - __bfloat162float(hb));
    hi = *(uint32_t*)&hp; lo = *(uint32_t*)&lp;
}

// ===================== fp32 -> bf16 hi/lo split =============================
__global__ void __launch_bounds__(256) split_kernel(
    const float* __restrict__ x, __nv_bfloat16* __restrict__ hi,
    __nv_bfloat16* __restrict__ lo, int n4)
{
    int i = blockIdx.x * 256 + threadIdx.x;
    if (i >= n4) return;
    float4 v = ((const float4*)x)[i];
    uint32_t h0, l0, h1, l1;
    split2(v.x, v.y, h0, l0);
    split2(v.z, v.w, h1, l1);
    uint2 hv, lv;
    hv.x = h0; hv.y = h1; lv.x = l0; lv.y = l1;
    ((uint2*)hi)[i] = hv;
    ((uint2*)lo)[i] = lv;
}

// ============================================================================
// mma.sync GEMM: Y = X @ W^T + bias, split-bf16 (hh + hl + lh).
// CTA 128x128, kChunk=32, 8 warps (32x64), double-buffered cp.async.
// MODE 0: head-split bf16 hi/lo outputs (Yh, Yl). MODE 1: fp32 [M,N] (Yf).
// ============================================================================
#define LDK   40
#define MAT_B (128 * LDK * 2)
#define BUF_B (4 * MAT_B)
#define PROJ_SMEM (2 * BUF_B)

template<int MODE>
__global__ void __launch_bounds__(256) mma_proj(
    const __nv_bfloat16* __restrict__ Xhi, const __nv_bfloat16* __restrict__ Xlo,
    const __nv_bfloat16* __restrict__ Whi, const __nv_bfloat16* __restrict__ Wlo,
    const float* __restrict__ bias, float* __restrict__ Yf,
    __nv_bfloat16* __restrict__ Yh, __nv_bfloat16* __restrict__ Yl)
{
    extern __shared__ char smem[];
    const int K = D_;
    int tid = threadIdx.x, wid = tid >> 5, lane = tid & 31;
    int bm = blockIdx.x * 128, bn = blockIdx.y * 128;
    int warp_m = (wid & 3) * 32, warp_n = (wid >> 2) * 64;

    uint32_t sbase = smem_u32(smem);

    int lrow = tid >> 1, lcol = (tid & 1) * 16;
    const __nv_bfloat16* gA_h = Xhi + (size_t)(bm + lrow) * K + lcol;
    const __nv_bfloat16* gA_l = Xlo + (size_t)(bm + lrow) * K + lcol;
    const __nv_bfloat16* gB_h = Whi + (size_t)(bn + lrow) * K + lcol;
    const __nv_bfloat16* gB_l = Wlo + (size_t)(bn + lrow) * K + lcol;
    uint32_t soff = (uint32_t)(lrow * LDK + lcol) * 2;

    auto issue_chunk = [&](int c, int buf) {
        uint32_t base = sbase + buf * BUF_B;
        int k0 = c * 32;
        #pragma unroll
        for (int h = 0; h < 2; h++) {
            uint32_t so = soff + h * 16;
            int go = k0 + h * 8;
            cp_async16(base + 0*MAT_B + so, gA_h + go);
            cp_async16(base + 1*MAT_B + so, gA_l + go);
            cp_async16(base + 2*MAT_B + so, gB_h + go);
            cp_async16(base + 3*MAT_B + so, gB_l + go);
        }
        cp_commit();
    };

    float acc[2][8][4];
    #pragma unroll
    for (int mf = 0; mf < 2; mf++)
        #pragma unroll
        for (int nf = 0; nf < 8; nf++)
            #pragma unroll
            for (int r = 0; r < 4; r++) acc[mf][nf][r] = 0.f;

    const int NCH = K / 32;
    issue_chunk(0, 0);
    int buf = 0;

    uint32_t a_off = (uint32_t)((warp_m + (lane & 15)) * LDK + (lane >> 4) * 8) * 2;
    uint32_t b_off = (uint32_t)((warp_n + ((lane >> 4) * 8) + (lane & 7)) * LDK
                                + (((lane >> 3) & 1) * 8)) * 2;

    for (int c = 0; c < NCH; c++) {
        if (c + 1 < NCH) { issue_chunk(c + 1, buf ^ 1); cp_wait<1>(); }
        else cp_wait<0>();
        __syncthreads();

        uint32_t base = sbase + buf * BUF_B;
        #pragma unroll
        for (int ks = 0; ks < 2; ks++) {
            uint32_t kso = (uint32_t)(ks * 16) * 2;
            uint32_t ah[2][4], al[2][4], bh[8][2], bl[8][2];
            #pragma unroll
            for (int mf = 0; mf < 2; mf++) {
                uint32_t ao = a_off + (uint32_t)(mf * 16 * LDK) * 2 + kso;
                ldm_x4(base + 0*MAT_B + ao, ah[mf][0], ah[mf][1], ah[mf][2], ah[mf][3]);
                ldm_x4(base + 1*MAT_B + ao, al[mf][0], al[mf][1], al[mf][2], al[mf][3]);
            }
            #pragma unroll
            for (int bg = 0; bg < 4; bg++) {
                uint32_t bo = b_off + (uint32_t)(bg * 16 * LDK) * 2 + kso;
                ldm_x4(base + 2*MAT_B + bo, bh[bg*2][0], bh[bg*2][1], bh[bg*2+1][0], bh[bg*2+1][1]);
                ldm_x4(base + 3*MAT_B + bo, bl[bg*2][0], bl[bg*2][1], bl[bg*2+1][0], bl[bg*2+1][1]);
            }
            #pragma unroll
            for (int mf = 0; mf < 2; mf++)
                #pragma unroll
                for (int nf = 0; nf < 8; nf++) {
                    mma_bf16(acc[mf][nf], ah[mf], bh[nf]);
                    mma_bf16(acc[mf][nf], ah[mf], bl[nf]);
                    mma_bf16(acc[mf][nf], al[mf], bh[nf]);
                }
        }
        __syncthreads();
        buf ^= 1;
    }

    int g = lane >> 2;
    #pragma unroll
    for (int nf = 0; nf < 8; nf++) {
        int n = bn + warp_n + nf * 8 + (lane & 3) * 2;
        float b0 = bias[n], b1 = bias[n + 1];
        #pragma unroll
        for (int mf = 0; mf < 2; mf++) {
            int m = bm + warp_m + mf * 16 + g;
            float2 o0, o1;
            o0.x = acc[mf][nf][0] + b0; o0.y = acc[mf][nf][1] + b1;
            o1.x = acc[mf][nf][2] + b0; o1.y = acc[mf][nf][3] + b1;
            if (MODE == 0) {
                int bb = m >> 10, s = m & 1023;
                int h = n >> 6, d = n & 63;
                size_t rb = (((size_t)bb * H_ + h) * S_);
                size_t i0 = (rb + s) * HD_ + d;
                size_t i1 = (rb + s + 8) * HD_ + d;
                uint32_t h0, l0, h1, l1;
                split2(o0.x, o0.y, h0, l0);
                split2(o1.x, o1.y, h1, l1);
                *(uint32_t*)&Yh[i0] = h0; *(uint32_t*)&Yl[i0] = l0;
                *(uint32_t*)&Yh[i1] = h1; *(uint32_t*)&Yl[i1] = l1;
            } else {
                *(float2*)&Yf[(size_t)m * D_ + n] = o0;
                *(float2*)&Yf[(size_t)(m + 8) * D_ + n] = o1;
            }
        }
    }
}

// ============================================================================
// scores = (Q@K^T)*0.125 masked.  Per (b,h), CTA 128x128, K=HD=64 resident.
// 8 warps, warp tile 32x64.  Inputs: bf16 hi/lo q, k [B,H,S,HD].
// ============================================================================
#define LDS2   72                        // padded row (bf16 elems), 144B
#define SC_MAT (128 * LDS2 * 2)          // 18432 B
#define SC_SMEM (4 * SC_MAT)             // 73728

__global__ void __launch_bounds__(256) scores_mma(
    const __nv_bfloat16* __restrict__ qh, const __nv_bfloat16* __restrict__ ql,
    const __nv_bfloat16* __restrict__ kh, const __nv_bfloat16* __restrict__ kl,
    const int* __restrict__ mask, float* __restrict__ attn)
{
    extern __shared__ char smem[];
    int bh = blockIdx.z;
    int b = bh / H_;
    int bq = blockIdx.x * 128, bk = blockIdx.y * 128;
    int tid = threadIdx.x, wid = tid >> 5, lane = tid & 31;
    int warp_m = (wid & 3) * 32, warp_n = (wid >> 2) * 64;
    uint32_t sbase = smem_u32(smem);

    const __nv_bfloat16* Qh = qh + ((size_t)bh * S_ + bq) * HD_;
    const __nv_bfloat16* Ql = ql + ((size_t)bh * S_ + bq) * HD_;
    const __nv_bfloat16* Kh = kh + ((size_t)bh * S_ + bk) * HD_;
    const __nv_bfloat16* Kl = kl + ((size_t)bh * S_ + bk) * HD_;

    #pragma unroll
    for (int t = 0; t < 4; t++) {
        int idx = tid + t * 256;
        int row = idx >> 3, pc = idx & 7;
        uint32_t so = (uint32_t)(row * LDS2 + pc * 8) * 2;
        size_t go = (size_t)row * HD_ + pc * 8;
        cp_async16(sbase + 0*SC_MAT + so, Qh + go);
        cp_async16(sbase + 1*SC_MAT + so, Ql + go);
        cp_async16(sbase + 2*SC_MAT + so, Kh + go);
        cp_async16(sbase + 3*SC_MAT + so, Kl + go);
    }
    cp_commit();

    float acc[2][8][4];
    #pragma unroll
    for (int mf = 0; mf < 2; mf++)
        #pragma unroll
        for (int nf = 0; nf < 8; nf++)
            #pragma unroll
            for (int r = 0; r < 4; r++) acc[mf][nf][r] = 0.f;

    uint32_t a_off = (uint32_t)((warp_m + (lane & 15)) * LDS2 + (lane >> 4) * 8) * 2;
    uint32_t b_off = (uint32_t)((warp_n + ((lane >> 4) * 8) + (lane & 7)) * LDS2
                                + (((lane >> 3) & 1) * 8)) * 2;

    cp_wait<0>();
    __syncthreads();

    #pragma unroll
    for (int ks = 0; ks < 4; ks++) {
        uint32_t kso = (uint32_t)(ks * 16) * 2;
        uint32_t ah[2][4], al[2][4], bhf[8][2], blf[8][2];
        #pragma unroll
        for (int mf = 0; mf < 2; mf++) {
            uint32_t ao = a_off + (uint32_t)(mf * 16 * LDS2) * 2 + kso;
            ldm_x4(sbase + 0*SC_MAT + ao, ah[mf][0], ah[mf][1], ah[mf][2], ah[mf][3]);
            ldm_x4(sbase + 1*SC_MAT + ao, al[mf][0], al[mf][1], al[mf][2], al[mf][3]);
        }
        #pragma unroll
        for (int bg = 0; bg < 4; bg++) {
            uint32_t bo = b_off + (uint32_t)(bg * 16 * LDS2) * 2 + kso;
            ldm_x4(sbase + 2*SC_MAT + bo, bhf[bg*2][0], bhf[bg*2][1], bhf[bg*2+1][0], bhf[bg*2+1][1]);
            ldm_x4(sbase + 3*SC_MAT + bo, blf[bg*2][0], blf[bg*2][1], blf[bg*2+1][0], blf[bg*2+1][1]);
        }
        #pragma unroll
        for (int mf = 0; mf < 2; mf++)
            #pragma unroll
            for (int nf = 0; nf < 8; nf++) {
                mma_bf16(acc[mf][nf], ah[mf], bhf[nf]);
                mma_bf16(acc[mf][nf], ah[mf], blf[nf]);
                mma_bf16(acc[mf][nf], al[mf], bhf[nf]);
            }
    }

    const int* mrow = mask + (size_t)b * S_;
    int g = lane >> 2;
    #pragma unroll
    for (int nf = 0; nf < 8; nf++) {
        int n = bk + warp_n + nf * 8 + (lane & 3) * 2;
        int m0 = mrow[n], m1 = mrow[n + 1];
        #pragma unroll
        for (int mf = 0; mf < 2; mf++) {
            int m = bq + warp_m + mf * 16 + g;
            float2 o0, o1;
            o0.x = (m0 == 0) ? -1e10f : acc[mf][nf][0] * 0.125f;
            o0.y = (m1 == 0) ? -1e10f : acc[mf][nf][1] * 0.125f;
            o1.x = (m0 == 0) ? -1e10f : acc[mf][nf][2] * 0.125f;
            o1.y = (m1 == 0) ? -1e10f : acc[mf][nf][3] * 0.125f;
            size_t rb = (size_t)bh * S_;
            *(float2*)&attn[(rb + m) * S_ + n] = o0;
            *(float2*)&attn[(rb + m + 8) * S_ + n] = o1;
        }
    }
}

// ============================================================================
// Softmax in place over rows of 1024 (unchanged).
// ============================================================================
__global__ void __launch_bounds__(256) softmax_kernel(float* __restrict__ attn)
{
    size_t row = blockIdx.x;
    float4* p = reinterpret_cast<float4*>(attn + row * S_);
    int tid = threadIdx.x, lane = tid & 31, wid = tid >> 5;
    __shared__ float red[8];

    float4 v = p[tid];
    float mx = fmaxf(fmaxf(v.x, v.y), fmaxf(v.z, v.w));
    #pragma unroll
    for (int o = 16; o > 0; o >>= 1) mx = fmaxf(mx, __shfl_xor_sync(0xffffffffu, mx, o));
    if (lane == 0) red[wid] = mx;
    __syncthreads();
    mx = red[0];
    #pragma unroll
    for (int i = 1; i < 8; i++) mx = fmaxf(mx, red[i]);
    __syncthreads();

    float e0 = __expf(v.x - mx), e1 = __expf(v.y - mx);
    float e2 = __expf(v.z - mx), e3 = __expf(v.w - mx);
    float s = e0 + e1 + e2 + e3;
    #pragma unroll
    for (int o = 16; o > 0; o >>= 1) s += __shfl_xor_sync(0xffffffffu, s, o);
    if (lane == 0) red[wid] = s;
    __syncthreads();
    float tot = red[0];
    #pragma unroll
    for (int i = 1; i < 8; i++) tot += red[i];
    float inv = 1.0f / tot;

    float4 o;
    o.x = e0 * inv; o.y = e1 * inv; o.z = e2 * inv; o.w = e3 * inv;
    p[tid] = o;
}

// ============================================================================
// ctx = attn @ V.  Per (b,h), CTA 128q x 64d, k-chunks of 64.
// attn fp32 converted to bf16 hi/lo in-kernel; V bf16 hi/lo via ldmatrix.trans.
// 8 warps, warp tile 32x32 (2 mfrag x 4 nfrag).
// ============================================================================
#define CX_AMAT (128 * LDS2 * 2)          // 18432
#define CX_VMAT (64 * LDS2 * 2)           // 9216
#define CX_SMEM (2 * CX_AMAT + 2 * CX_VMAT)  // 55296

__global__ void __launch_bounds__(256) ctx_mma(
    const float* __restrict__ attn,
    const __nv_bfloat16* __restrict__ vh, const __nv_bfloat16* __restrict__ vl)
{
    extern __shared__ char smem[];
    int bh = blockIdx.z;
    int b = bh / H_, h = bh % H_;
    int bq = blockIdx.x * 128;
    int tid = threadIdx.x, wid = tid >> 5, lane = tid & 31;
    int warp_m = (wid & 3) * 32, warp_n = (wid >> 2) * 32;
    uint32_t sbase = smem_u32(smem);
    uint32_t sAh = sbase, sAl = sbase + CX_AMAT;
    uint32_t sVh = sbase + 2*CX_AMAT, sVl = sbase + 2*CX_AMAT + CX_VMAT;

    const float* A = attn + ((size_t)bh * S_ + bq) * S_;
    const __nv_bfloat16* Vh = vh + (size_t)bh * S_ * HD_;
    const __nv_bfloat16* Vl = vl + (size_t)bh * S_ * HD_;

    float acc[2][4][4];
    #pragma unroll
    for (int mf = 0; mf < 2; mf++)
        #pragma unroll
        for (int nf = 0; nf < 4; nf++)
            #pragma unroll
            for (int r = 0; r < 4; r++) acc[mf][nf][r] = 0.f;

    uint32_t a_off = (uint32_t)((warp_m + (lane & 15)) * LDS2 + (lane >> 4) * 8) * 2;
    // V trans: row = k (lane&15), col = ng*16 + (lane>>4)*8
    uint32_t v_off = (uint32_t)((lane & 15) * LDS2 + (lane >> 4) * 8) * 2;

    for (int c = 0; c < 16; c++) {
        int k0 = c * 64;
        // V chunk via cp.async
        #pragma unroll
        for (int t = 0; t < 2; t++) {
            int idx = tid + t * 256;
            int row = idx >> 3, pc = idx & 7;
            uint32_t so = (uint32_t)(row * LDS2 + pc * 8) * 2;
            size_t go = (size_t)(k0 + row) * HD_ + pc * 8;
            cp_async16(sVh + so, Vh + go);
            cp_async16(sVl + so, Vl + go);
        }
        cp_commit();
        // attn chunk: fp32 -> bf16 hi/lo
        #pragma unroll
        for (int t = 0; t < 8; t++) {
            int idx = tid + t * 256;
            int row = idx >> 4, c4 = idx & 15;
            float4 v = *(const float4*)&A[(size_t)row * S_ + k0 + c4 * 4];
            uint32_t h0, l0, h1, l1;
            split2(v.x, v.y, h0, l0);
            split2(v.z, v.w, h1, l1);
            uint32_t so = (uint32_t)(row * LDS2 + c4 * 4) * 2;
            uint2 hv; hv.x = h0; hv.y = h1;
            uint2 lv; lv.x = l0; lv.y = l1;
            asm volatile("st.shared.v2.u32 [%0], {%1, %2};" :: "r"(sAh + so), "r"(hv.x), "r"(hv.y) : "memory");
            asm volatile("st.shared.v2.u32 [%0], {%1, %2};" :: "r"(sAl + so), "r"(lv.x), "r"(lv.y) : "memory");
        }
        cp_wait<0>();
        __syncthreads();

        #pragma unroll
        for (int ks = 0; ks < 4; ks++) {
            uint32_t kso = (uint32_t)(ks * 16) * 2;
            uint32_t ah[2][4], al[2][4], bhf[4][2], blf[4][2];
            #pragma unroll
            for (int mf = 0; mf < 2; mf++) {
                uint32_t ao = a_off + (uint32_t)(mf * 16 * LDS2) * 2 + kso;
                ldm_x4(sAh + ao, ah[mf][0], ah[mf][1], ah[mf][2], ah[mf][3]);
                ldm_x4(sAl + ao, al[mf][0], al[mf][1], al[mf][2], al[mf][3]);
            }
            #pragma unroll
            for (int ng = 0; ng < 2; ng++) {
                uint32_t vo = v_off + (uint32_t)(ks * 16 * LDS2) * 2
                            + (uint32_t)(warp_n + ng * 16) * 2;
                ldm_x4_t(sVh + vo, bhf[ng*2][0], bhf[ng*2][1], bhf[ng*2+1][0], bhf[ng*2+1][1]);
                ldm_x4_t(sVl + vo, blf[ng*2][0], blf[ng*2][1], blf[ng*2+1][0], blf[ng*2+1][1]);
            }
            #pragma unroll
            for (int mf = 0; mf < 2; mf++)
                #pragma unroll
                for (int nf = 0; nf < 4; nf++) {
                    mma_bf16(acc[mf][nf], ah[mf], bhf[nf]);
                    mma_bf16(acc[mf][nf], ah[mf], blf[nf]);
                    mma_bf16(acc[mf][nf], al[mf], bhf[nf]);
                }
        }
        __syncthreads();
    }

    int g = lane >> 2;
    #pragma unroll
    for (int nf = 0; nf < 4; nf++) {
        int n = warp_n + nf * 8 + (lane & 3) * 2;
        #pragma unroll
        for (int mf = 0; mf < 2; mf++) {
            int m = bq + warp_m + mf * 16 + g;
            float2 o0, o1;
            o0.x = acc[mf][nf][0]; o0.y = acc[mf][nf][1];
            o1.x = acc[mf][nf][2]; o1.y = acc[mf][nf][3];
            size_t r0 = ((size_t)b * S_ + m) * D_ + h * HD_ + n;
            size_t r1 = ((size_t)b * S_ + m + 8) * D_ + h * HD_ + n;
            *(float2*)&g_ctx[r0] = o0;
            *(float2*)&g_ctx[r1] = o1;
        }
    }
}

// ============================================================================
extern "C" void kernel_launch(void* const* d_in, const int* in_sizes, int n_in,
                              void* d_out, int out_size)
{
    const float* query = (const float*)d_in[0];
    const float* key_  = (const float*)d_in[1];
    const float* value = (const float*)d_in[2];
    const int*   mask  = (const int*)d_in[3];
    const float* Wq = (const float*)d_in[4];  const float* bq = (const float*)d_in[5];
    const float* Wk = (const float*)d_in[6];  const float* bk = (const float*)d_in[7];
    const float* Wv = (const float*)d_in[8];  const float* bv = (const float*)d_in[9];
    const float* Wo = (const float*)d_in[10]; const float* bo = (const float*)d_in[11];
    float* out = (float*)d_out;

    float *pctx, *pfb;
    __nv_bfloat16 *pxh, *pxl, *pwh, *pwl, *pqh, *pql, *pkh, *pkl, *pvh, *pvl;
    cudaGetSymbolAddress((void**)&pctx, g_ctx);
    cudaGetSymbolAddress((void**)&pfb,  g_attn_fb);
    cudaGetSymbolAddress((void**)&pxh,  g_xhi);
    cudaGetSymbolAddress((void**)&pxl,  g_xlo);
    cudaGetSymbolAddress((void**)&pwh,  g_whi);
    cudaGetSymbolAddress((void**)&pwl,  g_wlo);
    cudaGetSymbolAddress((void**)&pqh,  g_qh);
    cudaGetSymbolAddress((void**)&pql,  g_ql);
    cudaGetSymbolAddress((void**)&pkh,  g_kh);
    cudaGetSymbolAddress((void**)&pkl,  g_kl);
    cudaGetSymbolAddress((void**)&pvh,  g_vh);
    cudaGetSymbolAddress((void**)&pvl,  g_vl);

    static bool attr_set = false;
    if (!attr_set) {
        cudaFuncSetAttribute(mma_proj<0>, cudaFuncAttributeMaxDynamicSharedMemorySize, PROJ_SMEM);
        cudaFuncSetAttribute(mma_proj<1>, cudaFuncAttributeMaxDynamicSharedMemorySize, PROJ_SMEM);
        cudaFuncSetAttribute(scores_mma, cudaFuncAttributeMaxDynamicSharedMemorySize, SC_SMEM);
        cudaFuncSetAttribute(ctx_mma, cudaFuncAttributeMaxDynamicSharedMemorySize, CX_SMEM);
        attr_set = true;
    }

    const size_t OUT_E = (size_t)M_ * D_;
    const size_t ATT_E = (size_t)B_ * H_ * S_ * S_;
    float* attn = ((size_t)out_size >= OUT_E + ATT_E) ? (out + OUT_E) : pfb;

    const int NX4 = M_ * D_ / 4;
    const int NW4 = D_ * D_ / 4;
    dim3 gx((NX4 + 255) / 256), gw((NW4 + 255) / 256);
    dim3 gproj(M_ / 128, D_ / 128);

    // Q projection -> bf16 hi/lo head-split
    split_kernel<<<gx, 256>>>(query, pxh, pxl, NX4);
    split_kernel<<<gw, 256>>>(Wq, pwh, pwl, NW4);
    mma_proj<0><<<gproj, 256, PROJ_SMEM>>>(pxh, pxl, pwh, pwl, bq, nullptr, pqh, pql);
    // K projection
    split_kernel<<<gx, 256>>>(key_, pxh, pxl, NX4);
    split_kernel<<<gw, 256>>>(Wk, pwh, pwl, NW4);
    mma_proj<0><<<gproj, 256, PROJ_SMEM>>>(pxh, pxl, pwh, pwl, bk, nullptr, pkh, pkl);
    // V projection
    split_kernel<<<gx, 256>>>(value, pxh, pxl, NX4);
    split_kernel<<<gw, 256>>>(Wv, pwh, pwl, NW4);
    mma_proj<0><<<gproj, 256, PROJ_SMEM>>>(pxh, pxl, pwh, pwl, bv, nullptr, pvh, pvl);

    dim3 gsc(S_ / 128, S_ / 128, B_ * H_);
    scores_mma<<<gsc, 256, SC_SMEM>>>(pqh, pql, pkh, pkl, mask, attn);

    softmax_kernel<<<B_ * H_ * S_, 256>>>(attn);

    dim3 gctx(S_ / 128, 1, B_ * H_);
    ctx_mma<<<gctx, 256, CX_SMEM>>>(attn, pvh, pvl);

    // Output projection (fp32 out)
    split_kernel<<<gx, 256>>>(pctx, pxh, pxl, NX4);
    split_kernel<<<gw, 256>>>(Wo, pwh, pwl, NW4);
    mma_proj<1><<<gproj, 256, PROJ_SMEM>>>(pxh, pxl, pwh, pwl, bo, out, nullptr, nullptr);
}